// round 16
// baseline (speedup 1.0000x reference)
#include <cuda_runtime.h>
#include <math.h>

// ProbabilisticMap: out[b][x][y][t] = N((x,y); mean(b,t), cov(b,t)) for a
// Bezier mixture of 8 control-point Gaussians.
// Shapes: cp_means (8,128,2), cp_covariances (8,128,2,2), out (128,64,64,50) fp32.
//
// R15: R14 dataflow (register-resident t-pair coefficients, Horner-in-y,
// contiguous STG.64 stream, one barrier) with a better schedule:
//   - TPB=128 (4 warps), 2048 CTAs: ~13.8 CTAs/SM, work-stealing smooths the
//     tail (R14's 1024 big CTAs achieved only 59% occupancy).
//   - 2 y-rows per loop iteration: 8 FMA + 4 EX2 + 2 STG per body -> double
//     the independent work between dependent MUFU results.

#define MAP_W 64
#define MAP_H 64
#define MAP_T 50
#define NUM_CP 8
#define BATCH 128

#define TPB 128                                      // 4 warps
#define X_PER_BLOCK 4                                // one x per warp
#define BLOCKS_PER_B (MAP_W / X_PER_BLOCK)           // 16
#define NUM_BLOCKS   (BATCH * BLOCKS_PER_B)          // 2048

__device__ __forceinline__ float ex2(float x) {
    float r;
    asm("ex2.approx.ftz.f32 %0, %1;" : "=f"(r) : "f"(x));
    return r;
}

__global__ __launch_bounds__(TPB, 12)
void probmap_kernel(const float* __restrict__ cp_means,
                    const float* __restrict__ cp_covs,
                    float* __restrict__ out)
{
    __shared__ float4 sP4[MAP_T];                    // (mx, my, c0, c1)
    __shared__ float2 sP2[MAP_T];                    // (c2, ls)

    const int tid = threadIdx.x;
    const int b   = blockIdx.x >> 4;                 // 16 blocks per batch
    const int x0  = (blockIdx.x & 15) * X_PER_BLOCK; // first x of this block

    // ---- Phase 0: per-t parameters (threads 0..49) ----
    if (tid < MAP_T) {
        const float tt = (float)tid * (1.0f / (float)(MAP_T - 1));
        const float u  = 1.0f - tt;
        const float C[NUM_CP] = {1.f, 7.f, 21.f, 35.f, 35.f, 21.f, 7.f, 1.f};

        float up[NUM_CP];
        up[0] = 1.0f;
#pragma unroll
        for (int i = 1; i < NUM_CP; i++) up[i] = up[i - 1] * u;

        float mx = 0.f, my = 0.f;
        float ca = 0.f, cb = 0.f, cc = 0.f, cd = 0.f;
        float t_pow = 1.0f;
#pragma unroll
        for (int i = 0; i < NUM_CP; i++) {
            const float bas = C[i] * t_pow * up[NUM_CP - 1 - i];
            t_pow *= tt;
            const float b2 = bas * bas;
            const float* m  = cp_means + (i * BATCH + b) * 2;   // warp-broadcast LDG
            const float* cv = cp_covs  + (i * BATCH + b) * 4;
            mx = fmaf(bas, m[0], mx);
            my = fmaf(bas, m[1], my);
            ca = fmaf(b2, cv[0], ca);
            cb = fmaf(b2, cv[1], cb);
            cc = fmaf(b2, cv[2], cc);
            cd = fmaf(b2, cv[3], cd);
        }
        const float det     = ca * cd - cb * cc;
        const float inv_det = 1.0f / det;
        const float HL2E    = 0.5f * 1.4426950408889634f;      // 0.5*log2(e)
        // exponent-space: s = c0*dx^2 + c1*dx*dy + c2*dy^2 + ls ; out = exp2(s)
        const float c0 = -HL2E * cd * inv_det;
        const float c1 =  HL2E * (cb + cc) * inv_det;
        const float c2 = -HL2E * ca * inv_det;
        const float ls = -0.5f * __log2f(39.478417604357434f * det);
        sP4[tid] = make_float4(mx, my, c0, c1);
        sP2[tid] = make_float2(c2, ls);
    }
    __syncthreads();                                 // the ONLY barrier

    const int w = tid >> 5;                          // warp 0..3
    const int l = tid & 31;
    const bool valid = (l < 25);
    const int tA = valid ? 2 * l : 0;                // lane's t-pair (clamped)

    // Coefficients live in registers for the whole kernel.
    const float4 a4 = sP4[tA];     const float2 a2 = sP2[tA];
    const float4 b4 = sP4[tA + 1]; const float2 b2 = sP2[tA + 1];

    const int   x  = x0 + w;                         // warp's x-slice
    const float xf = (float)x;

    // Per-(t,x) Horner coefficients: s(y) = c2*y^2 + Bp*y + Cp (amortized over 64 y)
    const float dxA  = xf - a4.x;
    const float cdxA = a4.w * dxA;
    const float CpA  = fmaf(a4.y, fmaf(a2.x, a4.y, -cdxA),
                            fmaf(a4.z * dxA, dxA, a2.y));
    const float BpA  = fmaf(-a2.x, a4.y + a4.y, cdxA);

    const float dxB  = xf - b4.x;
    const float cdxB = b4.w * dxB;
    const float CpB  = fmaf(b4.y, fmaf(b2.x, b4.y, -cdxB),
                            fmaf(b4.z * dxB, dxB, b2.y));
    const float BpB  = fmaf(-b2.x, b4.y + b4.y, cdxB);

    // Lane writes out[b][x][y][2l..2l+1]; warp covers 200 contiguous bytes per
    // y, y-steps contiguous -> sequential store stream. 2 rows per iteration.
    float* op = out + (((size_t)b * MAP_W + x) * MAP_H) * MAP_T + tA;

#pragma unroll 4
    for (int y = 0; y < MAP_H; y += 2) {
        const float y0 = (float)y;
        const float y1 = (float)(y + 1);

        const float s00 = fmaf(fmaf(a2.x, y0, BpA), y0, CpA);
        const float s01 = fmaf(fmaf(b2.x, y0, BpB), y0, CpB);
        const float s10 = fmaf(fmaf(a2.x, y1, BpA), y1, CpA);
        const float s11 = fmaf(fmaf(b2.x, y1, BpB), y1, CpB);

        float2 r0, r1;
        r0.x = ex2(s00); r0.y = ex2(s01);
        r1.x = ex2(s10); r1.y = ex2(s11);

        if (valid) {
            __stcs((float2*)(op + (size_t)y * MAP_T), r0);        // STG.64
            __stcs((float2*)(op + (size_t)(y + 1) * MAP_T), r1);  // STG.64
        }
    }
}

extern "C" void kernel_launch(void* const* d_in, const int* in_sizes, int n_in,
                              void* d_out, int out_size)
{
    const float* cp_means = (const float*)d_in[0];  // (8,128,2)
    const float* cp_covs  = (const float*)d_in[1];  // (8,128,2,2)
    float* out = (float*)d_out;                     // (128,64,64,50)
    (void)in_sizes; (void)n_in; (void)out_size;

    probmap_kernel<<<NUM_BLOCKS, TPB>>>(cp_means, cp_covs, out);
}